// round 3
// baseline (speedup 1.0000x reference)
#include <cuda_runtime.h>
#include <cstdint>
#include <math.h>

// Problem constants
//  B=4, L=1024, E=1024, H=16, D=64, HID=1024, R=4
//  inputs: query, rels, attn_mask, key_padding_mask, proj_w, proj_b, out_w, out_b, rels_bias
//  output: concat(out [4,1024,1024], w [4,1024,1024,16]) as float32

// ---------------------------------------------------------------------------
// Scratch (static device arrays; no allocations allowed)
// ---------------------------------------------------------------------------
__device__ float g_Q[4u * 16u * 1024u * 64u];      // [b][h][i][d]
__device__ float g_Kb[4u * 16u * 1024u * 64u];     // [b][h][j][d]
__device__ float g_TV[4u * 16u * 1024u * 64u];     // tanh(v)  [b][h][j][d]
__device__ float g_SG[4u * 1024u * 16u * 64u];     // sigmoid(g) [b][i][h][d] (== [b][i][hd])
__device__ float g_gated[4u * 1024u * 1024u];      // [b][i][hd]
__device__ float g_S[67108864u];                   // scores  [b][h][i][j]  (256 MB)
__device__ int   g_kpm_mode;                       // 0=32-bit word, 1=u8, 2=u16 (bf16)

// ---------------------------------------------------------------------------
// Helpers
// ---------------------------------------------------------------------------
__device__ __forceinline__ uint32_t f2tf(float x) {
    uint32_t r;
    asm("cvt.rna.tf32.f32 %0, %1;" : "=r"(r) : "f"(x));
    return r;
}

__device__ __forceinline__ void mma_tf32(float (&d)[4], const uint32_t (&a)[4],
                                         const uint32_t (&b)[2]) {
    asm volatile(
        "mma.sync.aligned.m16n8k8.row.col.f32.tf32.tf32.f32 "
        "{%0,%1,%2,%3}, {%4,%5,%6,%7}, {%8,%9}, {%0,%1,%2,%3};\n"
        : "+f"(d[0]), "+f"(d[1]), "+f"(d[2]), "+f"(d[3])
        : "r"(a[0]), "r"(a[1]), "r"(a[2]), "r"(a[3]), "r"(b[0]), "r"(b[1]));
}

// ---------------------------------------------------------------------------
// key_padding_mask dtype probe (bool may be serialized as u8 / i32 / f32 / bf16)
// Reads only the first 4KB, safe for all candidate layouts (min buffer 4MB).
// ---------------------------------------------------------------------------
__global__ void detect_kpm_kernel(const unsigned int* __restrict__ kpm) {
    __shared__ int s_f32, s_bf16, s_u8;
    if (threadIdx.x == 0) { s_f32 = 0; s_bf16 = 0; s_u8 = 0; }
    __syncthreads();
    for (int i = threadIdx.x; i < 1024; i += blockDim.x) {
        unsigned int w = kpm[i];
        if (w == 0x3F800000u) atomicOr(&s_f32, 1);
        else if ((w & 0xFFFFu) == 0x3F80u || (w >> 16) == 0x3F80u) atomicOr(&s_bf16, 1);
        else if (w > 1u) atomicOr(&s_u8, 1);
    }
    __syncthreads();
    if (threadIdx.x == 0) {
        int mode = 0;                       // int32 / float32: 4-byte word != 0
        if (s_bf16) mode = 2;               // bf16 halfwords
        else if (s_f32) mode = 0;
        else if (s_u8) mode = 1;            // packed bytes
        g_kpm_mode = mode;
    }
}

// ---------------------------------------------------------------------------
// tf32 GEMM: C[m,n] = sum_k A[m,k] * B[n,k]  (both K-major), 128x128x32 tiles
//   mode 0: A=query[4096,1024], B=proj_w[4096,1024], epilogue splits QKVG
//   mode 1: batched (z=b*16+h): A=g_Q[z], B=g_Kb[z], K=64, C=g_S[z]
//   mode 2: A=g_gated[4096,1024], B=out_w[1024,1024], C=d_out + out_b
// ---------------------------------------------------------------------------
__global__ __launch_bounds__(256, 1)
void gemm_tf32_kernel(int mode, const float* __restrict__ Aext,
                      const float* __restrict__ Bext,
                      const float* __restrict__ bias, float* __restrict__ Cext) {
    __shared__ uint32_t As[128][36];   // padded: conflict-free fragment loads
    __shared__ uint32_t Bs[128][36];

    const int tid = threadIdx.x;
    const int warp = tid >> 5, lane = tid & 31;
    const int wm = warp >> 1, wn = warp & 1;     // 4x2 warp grid
    const int r = lane >> 2, c = lane & 3;

    const float* Ap; const float* Bp; int lda, ldb, Kd;
    if (mode == 1) {
        size_t off = (size_t)blockIdx.z * 65536u;
        Ap = g_Q + off; Bp = g_Kb + off; lda = 64; ldb = 64; Kd = 64;
    } else if (mode == 2) {
        Ap = g_gated; Bp = Bext; lda = 1024; ldb = 1024; Kd = 1024;
    } else {
        Ap = Aext; Bp = Bext; lda = 1024; ldb = 1024; Kd = 1024;
    }
    const int m0 = blockIdx.y * 128;
    const int n0 = blockIdx.x * 128;

    float acc[2][8][4];
#pragma unroll
    for (int mt = 0; mt < 2; ++mt)
#pragma unroll
        for (int nt = 0; nt < 8; ++nt)
#pragma unroll
            for (int e = 0; e < 4; ++e) acc[mt][nt][e] = 0.f;

    const int kv4 = (tid & 7) * 4;   // k-vector offset within tile
    const int rb = tid >> 3;         // base row (0..31), +32 per q

    float4 pa[4], pb[4];
    auto load_tile = [&](int kb) {
#pragma unroll
        for (int q = 0; q < 4; ++q) {
            int row = rb + q * 32;
            pa[q] = *reinterpret_cast<const float4*>(Ap + (size_t)(m0 + row) * lda + kb * 32 + kv4);
            pb[q] = *reinterpret_cast<const float4*>(Bp + (size_t)(n0 + row) * ldb + kb * 32 + kv4);
        }
    };
    auto store_tile = [&]() {
#pragma unroll
        for (int q = 0; q < 4; ++q) {
            int row = rb + q * 32;
            As[row][kv4 + 0] = f2tf(pa[q].x); As[row][kv4 + 1] = f2tf(pa[q].y);
            As[row][kv4 + 2] = f2tf(pa[q].z); As[row][kv4 + 3] = f2tf(pa[q].w);
            Bs[row][kv4 + 0] = f2tf(pb[q].x); Bs[row][kv4 + 1] = f2tf(pb[q].y);
            Bs[row][kv4 + 2] = f2tf(pb[q].z); Bs[row][kv4 + 3] = f2tf(pb[q].w);
        }
    };

    const int nk = Kd >> 5;
    load_tile(0);
    store_tile();
    __syncthreads();

    for (int kb = 0; kb < nk; ++kb) {
        if (kb + 1 < nk) load_tile(kb + 1);
#pragma unroll
        for (int ks = 0; ks < 4; ++ks) {
            const int kk = ks * 8;
            uint32_t af[2][4], bf[8][2];
#pragma unroll
            for (int mt = 0; mt < 2; ++mt) {
                int row0 = wm * 32 + mt * 16 + r;
                af[mt][0] = As[row0][kk + c];
                af[mt][1] = As[row0 + 8][kk + c];
                af[mt][2] = As[row0][kk + c + 4];
                af[mt][3] = As[row0 + 8][kk + c + 4];
            }
#pragma unroll
            for (int nt = 0; nt < 8; ++nt) {
                int col0 = wn * 64 + nt * 8 + r;
                bf[nt][0] = Bs[col0][kk + c];
                bf[nt][1] = Bs[col0][kk + c + 4];
            }
#pragma unroll
            for (int mt = 0; mt < 2; ++mt)
#pragma unroll
                for (int nt = 0; nt < 8; ++nt)
                    mma_tf32(acc[mt][nt], af[mt], bf[nt]);
        }
        __syncthreads();
        if (kb + 1 < nk) { store_tile(); __syncthreads(); }
    }

    // epilogue
#pragma unroll
    for (int mt = 0; mt < 2; ++mt)
#pragma unroll
        for (int nt = 0; nt < 8; ++nt)
#pragma unroll
            for (int e = 0; e < 4; ++e) {
                int row = m0 + wm * 32 + mt * 16 + r + ((e >> 1) << 3);
                int col = n0 + wn * 64 + nt * 8 + 2 * c + (e & 1);
                float v = acc[mt][nt][e];
                if (mode == 0) {
                    v += bias[col];
                    int sec = col >> 10, cc = col & 1023;
                    int h = cc >> 6, d = cc & 63;
                    int b = row >> 10, i = row & 1023;
                    size_t hidx = (((size_t)b * 16 + h) * 1024 + i) * 64 + d;
                    if (sec == 0) g_Q[hidx] = v;
                    else if (sec == 1) g_Kb[hidx] = v;
                    else if (sec == 2) g_TV[hidx] = tanhf(v);
                    else g_SG[((size_t)(b * 1024 + i) * 16 + h) * 64 + d] =
                             1.0f / (1.0f + __expf(-v));
                } else if (mode == 1) {
                    g_S[(size_t)blockIdx.z * 1048576u + (size_t)row * 1024 + col] = v;
                } else {
                    Cext[(size_t)row * 1024 + col] = v + bias[col];
                }
            }
}

// ---------------------------------------------------------------------------
// K3: softmax over heads + w output + PV accumulation + gating
// CTA = (b, 32 i-rows), 512 threads. 16 warps == 16 heads in phase 2.
// ---------------------------------------------------------------------------
__global__ __launch_bounds__(512, 1)
void attn_wpv_kernel(const float* __restrict__ rels,
                     const float* __restrict__ attn_mask,
                     const void* __restrict__ kpm,
                     const float* __restrict__ rels_bias,
                     float* __restrict__ d_out) {
    __shared__ float wsh[16][16][33];   // [h][j][i] padded (2-way max conflicts)
    __shared__ float sbias[4][16];

    const int tid = threadIdx.x;
    const int warp = tid >> 5, lane = tid & 31;
    const int b = blockIdx.y;
    const int i0 = blockIdx.x * 32;

    if (tid < 64) sbias[tid >> 4][tid & 15] = rels_bias[tid];  // [r][h]
    const int kmode = g_kpm_mode;

    float4 acc[16];
#pragma unroll
    for (int q = 0; q < 16; ++q) acc[q] = make_float4(0.f, 0.f, 0.f, 0.f);

    const int ip = tid >> 4;   // 0..31 : i within tile (phase 1)
    const int jp = tid & 15;   // 0..15 : j within tile (phase 1)
    const int i1 = i0 + ip;
    const size_t sbase0 = (size_t)b * 16777216u + (size_t)i1 * 1024u;  // S base
    const size_t mbase  = (size_t)b * 1048576u + (size_t)i1 * 1024u;   // masks base
    const size_t wout0  = 4194304u;                                    // B*L*E

    const float* tvb = g_TV + (size_t)(b * 16 + warp) * 65536u;

    for (int j0 = 0; j0 < 1024; j0 += 16) {
        __syncthreads();   // protect wsh reuse
        // ---- phase 1: softmax over heads, write w ----
        {
            const int j = j0 + jp;
            float s[16];
            const size_t sb = sbase0 + j;
#pragma unroll
            for (int h = 0; h < 16; ++h) s[h] = g_S[sb + (size_t)h * 1048576u];
            const float4 rv = *reinterpret_cast<const float4*>(rels + (mbase + j) * 4);
            const float am = attn_mask[mbase + j];
            bool keep;
            if (kmode == 1)
                keep = reinterpret_cast<const unsigned char*>(kpm)[mbase + j] != 0;
            else if (kmode == 2)
                keep = reinterpret_cast<const unsigned short*>(kpm)[mbase + j] != 0;
            else
                keep = reinterpret_cast<const unsigned int*>(kpm)[mbase + j] != 0u;

            float mx = -1e30f;
#pragma unroll
            for (int h = 0; h < 16; ++h) {
                s[h] = (s[h] + rv.x * sbias[0][h] + rv.y * sbias[1][h]
                             + rv.z * sbias[2][h] + rv.w * sbias[3][h]) * 0.125f;
                mx = fmaxf(mx, s[h]);
            }
            float sum = 0.f;
#pragma unroll
            for (int h = 0; h < 16; ++h) { s[h] = __expf(s[h] - mx); sum += s[h]; }
            const float scale = keep ? (__expf(am) / sum) : 0.f;
#pragma unroll
            for (int h = 0; h < 16; ++h) { s[h] *= scale; wsh[h][jp][ip] = s[h]; }
            float* wp = d_out + wout0 + (mbase + j) * 16;
#pragma unroll
            for (int h4 = 0; h4 < 4; ++h4) {
                float4 wv;
                wv.x = s[h4 * 4 + 0]; wv.y = s[h4 * 4 + 1];
                wv.z = s[h4 * 4 + 2]; wv.w = s[h4 * 4 + 3];
                reinterpret_cast<float4*>(wp)[h4] = wv;
            }
        }
        __syncthreads();
        // ---- phase 2: attn_out accumulation (warp == head, lane == i) ----
        {
            const float* tv = tvb + (size_t)j0 * 64;
#pragma unroll 2
            for (int jj = 0; jj < 16; ++jj) {
                const float wgt = wsh[warp][jj][lane];
                const float4* tvv = reinterpret_cast<const float4*>(tv + jj * 64);
#pragma unroll
                for (int q = 0; q < 16; ++q) {
                    float4 t = tvv[q];
                    acc[q].x = fmaf(wgt, t.x, acc[q].x);
                    acc[q].y = fmaf(wgt, t.y, acc[q].y);
                    acc[q].z = fmaf(wgt, t.z, acc[q].z);
                    acc[q].w = fmaf(wgt, t.w, acc[q].w);
                }
            }
        }
    }

    // ---- epilogue: gate with sigmoid(g), store for final projection ----
    {
        const size_t gi = ((size_t)(b * 1024 + i0 + lane) * 16 + warp) * 64;
        const float4* sg = reinterpret_cast<const float4*>(g_SG + gi);
        float4* gp = reinterpret_cast<float4*>(g_gated + gi);
#pragma unroll
        for (int q = 0; q < 16; ++q) {
            float4 s4 = sg[q];
            float4 o;
            o.x = acc[q].x * s4.x; o.y = acc[q].y * s4.y;
            o.z = acc[q].z * s4.z; o.w = acc[q].w * s4.w;
            gp[q] = o;
        }
    }
}

// ---------------------------------------------------------------------------
// launch
// ---------------------------------------------------------------------------
extern "C" void kernel_launch(void* const* d_in, const int* in_sizes, int n_in,
                              void* d_out, int out_size) {
    (void)in_sizes; (void)n_in; (void)out_size;
    const float* query     = (const float*)d_in[0];
    const float* rels      = (const float*)d_in[1];
    const float* attn_mask = (const float*)d_in[2];
    const void*  kpm       = d_in[3];
    const float* proj_w    = (const float*)d_in[4];
    const float* proj_b    = (const float*)d_in[5];
    const float* out_w     = (const float*)d_in[6];
    const float* out_b     = (const float*)d_in[7];
    const float* rels_bias = (const float*)d_in[8];
    float* out = (float*)d_out;

    // 0) detect key_padding_mask storage format
    detect_kpm_kernel<<<1, 256>>>((const unsigned int*)kpm);
    // 1) fused QKVG projection (+tanh/sigmoid epilogue)
    gemm_tf32_kernel<<<dim3(32, 32, 1), 256>>>(0, query, proj_w, proj_b, nullptr);
    // 2) scores S = Q K^T per (b,h)
    gemm_tf32_kernel<<<dim3(8, 8, 64), 256>>>(1, nullptr, nullptr, nullptr, nullptr);
    // 3) softmax-over-heads + w output + PV + gating
    attn_wpv_kernel<<<dim3(32, 4, 1), 512>>>(rels, attn_mask, kpm, rels_bias, out);
    // 4) output projection
    gemm_tf32_kernel<<<dim3(8, 32, 1), 256>>>(2, nullptr, out_w, out_b, out);
}

// round 5
// speedup vs baseline: 1.8154x; 1.8154x over previous
#include <cuda_runtime.h>
#include <cstdint>
#include <math.h>

// Problem constants
//  B=4, L=1024, E=1024, H=16, D=64, HID=1024, R=4
//  output: concat(out [4,1024,1024], w [4,1024,1024,16]) as float32

// ---------------------------------------------------------------------------
// Scratch (static device arrays; no allocations allowed)
// ---------------------------------------------------------------------------
__device__ float g_Q[4u * 16u * 1024u * 64u];      // [b][h][i][d]
__device__ float g_Kb[4u * 16u * 1024u * 64u];     // [b][h][j][d]
__device__ float g_TV[4u * 16u * 1024u * 64u];     // tanh(v)  [b][h][j][d]
__device__ float g_SG[4u * 1024u * 16u * 64u];     // sigmoid(g) [b][i][h][d]
__device__ float g_gated[4u * 1024u * 1024u];      // [b][i][hd]
__device__ float g_S[67108864u];                   // scores  [b][h][i][j]  (256 MB)
__device__ int   g_kpm_mode;                       // 0=32-bit word, 1=u8, 2=u16

// ---------------------------------------------------------------------------
// Helpers
// ---------------------------------------------------------------------------
__device__ __forceinline__ uint32_t f2tf(float x) {
    uint32_t r;
    asm("cvt.rna.tf32.f32 %0, %1;" : "=r"(r) : "f"(x));
    return r;
}

__device__ __forceinline__ void mma_tf32(float (&d)[4], const uint32_t (&a)[4],
                                         const uint32_t (&b)[2]) {
    asm volatile(
        "mma.sync.aligned.m16n8k8.row.col.f32.tf32.tf32.f32 "
        "{%0,%1,%2,%3}, {%4,%5,%6,%7}, {%8,%9}, {%0,%1,%2,%3};\n"
        : "+f"(d[0]), "+f"(d[1]), "+f"(d[2]), "+f"(d[3])
        : "r"(a[0]), "r"(a[1]), "r"(a[2]), "r"(a[3]), "r"(b[0]), "r"(b[1]));
}

// ---------------------------------------------------------------------------
// key_padding_mask dtype probe
// ---------------------------------------------------------------------------
__global__ void detect_kpm_kernel(const unsigned int* __restrict__ kpm) {
    __shared__ int s_f32, s_bf16, s_u8;
    if (threadIdx.x == 0) { s_f32 = 0; s_bf16 = 0; s_u8 = 0; }
    __syncthreads();
    for (int i = threadIdx.x; i < 1024; i += blockDim.x) {
        unsigned int w = kpm[i];
        if (w == 0x3F800000u) atomicOr(&s_f32, 1);
        else if ((w & 0xFFFFu) == 0x3F80u || (w >> 16) == 0x3F80u) atomicOr(&s_bf16, 1);
        else if (w > 1u) atomicOr(&s_u8, 1);
    }
    __syncthreads();
    if (threadIdx.x == 0) {
        int mode = 0;
        if (s_bf16) mode = 2;
        else if (s_f32) mode = 0;
        else if (s_u8) mode = 1;
        g_kpm_mode = mode;
    }
}

// ---------------------------------------------------------------------------
// tf32 GEMM: C[m,n] = sum_k A[m,k] * B[n,k], 128x128x32 tiles (unchanged)
// ---------------------------------------------------------------------------
__global__ __launch_bounds__(256, 1)
void gemm_tf32_kernel(int mode, const float* __restrict__ Aext,
                      const float* __restrict__ Bext,
                      const float* __restrict__ bias, float* __restrict__ Cext) {
    __shared__ uint32_t As[128][36];
    __shared__ uint32_t Bs[128][36];

    const int tid = threadIdx.x;
    const int warp = tid >> 5, lane = tid & 31;
    const int wm = warp >> 1, wn = warp & 1;
    const int r = lane >> 2, c = lane & 3;

    const float* Ap; const float* Bp; int lda, ldb, Kd;
    if (mode == 1) {
        size_t off = (size_t)blockIdx.z * 65536u;
        Ap = g_Q + off; Bp = g_Kb + off; lda = 64; ldb = 64; Kd = 64;
    } else if (mode == 2) {
        Ap = g_gated; Bp = Bext; lda = 1024; ldb = 1024; Kd = 1024;
    } else {
        Ap = Aext; Bp = Bext; lda = 1024; ldb = 1024; Kd = 1024;
    }
    const int m0 = blockIdx.y * 128;
    const int n0 = blockIdx.x * 128;

    float acc[2][8][4];
#pragma unroll
    for (int mt = 0; mt < 2; ++mt)
#pragma unroll
        for (int nt = 0; nt < 8; ++nt)
#pragma unroll
            for (int e = 0; e < 4; ++e) acc[mt][nt][e] = 0.f;

    const int kv4 = (tid & 7) * 4;
    const int rb = tid >> 3;

    float4 pa[4], pb[4];
    auto load_tile = [&](int kb) {
#pragma unroll
        for (int q = 0; q < 4; ++q) {
            int row = rb + q * 32;
            pa[q] = *reinterpret_cast<const float4*>(Ap + (size_t)(m0 + row) * lda + kb * 32 + kv4);
            pb[q] = *reinterpret_cast<const float4*>(Bp + (size_t)(n0 + row) * ldb + kb * 32 + kv4);
        }
    };
    auto store_tile = [&]() {
#pragma unroll
        for (int q = 0; q < 4; ++q) {
            int row = rb + q * 32;
            As[row][kv4 + 0] = f2tf(pa[q].x); As[row][kv4 + 1] = f2tf(pa[q].y);
            As[row][kv4 + 2] = f2tf(pa[q].z); As[row][kv4 + 3] = f2tf(pa[q].w);
            Bs[row][kv4 + 0] = f2tf(pb[q].x); Bs[row][kv4 + 1] = f2tf(pb[q].y);
            Bs[row][kv4 + 2] = f2tf(pb[q].z); Bs[row][kv4 + 3] = f2tf(pb[q].w);
        }
    };

    const int nk = Kd >> 5;
    load_tile(0);
    store_tile();
    __syncthreads();

    for (int kb = 0; kb < nk; ++kb) {
        if (kb + 1 < nk) load_tile(kb + 1);
#pragma unroll
        for (int ks = 0; ks < 4; ++ks) {
            const int kk = ks * 8;
            uint32_t af[2][4], bf[8][2];
#pragma unroll
            for (int mt = 0; mt < 2; ++mt) {
                int row0 = wm * 32 + mt * 16 + r;
                af[mt][0] = As[row0][kk + c];
                af[mt][1] = As[row0 + 8][kk + c];
                af[mt][2] = As[row0][kk + c + 4];
                af[mt][3] = As[row0 + 8][kk + c + 4];
            }
#pragma unroll
            for (int nt = 0; nt < 8; ++nt) {
                int col0 = wn * 64 + nt * 8 + r;
                bf[nt][0] = Bs[col0][kk + c];
                bf[nt][1] = Bs[col0][kk + c + 4];
            }
#pragma unroll
            for (int mt = 0; mt < 2; ++mt)
#pragma unroll
                for (int nt = 0; nt < 8; ++nt)
                    mma_tf32(acc[mt][nt], af[mt], bf[nt]);
        }
        __syncthreads();
        if (kb + 1 < nk) { store_tile(); __syncthreads(); }
    }

#pragma unroll
    for (int mt = 0; mt < 2; ++mt)
#pragma unroll
        for (int nt = 0; nt < 8; ++nt)
#pragma unroll
            for (int e = 0; e < 4; ++e) {
                int row = m0 + wm * 32 + mt * 16 + r + ((e >> 1) << 3);
                int col = n0 + wn * 64 + nt * 8 + 2 * c + (e & 1);
                float v = acc[mt][nt][e];
                if (mode == 0) {
                    v += bias[col];
                    int sec = col >> 10, cc = col & 1023;
                    int h = cc >> 6, d = cc & 63;
                    int b = row >> 10, i = row & 1023;
                    size_t hidx = (((size_t)b * 16 + h) * 1024 + i) * 64 + d;
                    if (sec == 0) g_Q[hidx] = v;
                    else if (sec == 1) g_Kb[hidx] = v;
                    else if (sec == 2) g_TV[hidx] = tanhf(v);
                    else g_SG[((size_t)(b * 1024 + i) * 16 + h) * 64 + d] =
                             1.0f / (1.0f + __expf(-v));
                } else if (mode == 1) {
                    g_S[(size_t)blockIdx.z * 1048576u + (size_t)row * 1024 + col] = v;
                } else {
                    Cext[(size_t)row * 1024 + col] = v + bias[col];
                }
            }
}

// ---------------------------------------------------------------------------
// K3: softmax over heads + w output + tensor-core PV + gating
// CTA = (b, 32 i-rows), 512 threads, 16 warps == 16 heads.
// Dynamic smem layout:
//   wsh : uint32[16][32][20]  (tf32 w, A-fragment layout, conflict-free pad 20)
//   tvsh: uint32[16][16][72]  (tf32 tanhV tile per head, B-frag pad 72)
// ---------------------------------------------------------------------------
#define WSH_SZ  (16 * 32 * 20)
#define TVSH_SZ (16 * 16 * 72)
#define K3_SMEM ((WSH_SZ + TVSH_SZ) * 4)

__global__ __launch_bounds__(512, 1)
void attn_wpv_kernel(const float* __restrict__ rels,
                     const float* __restrict__ attn_mask,
                     const void* __restrict__ kpm,
                     const float* __restrict__ rels_bias,
                     float* __restrict__ d_out) {
    extern __shared__ uint32_t smemu[];
    uint32_t* wsh  = smemu;            // [h][i(32)][20], j in [0,16)
    uint32_t* tvsh = smemu + WSH_SZ;   // [h][j(16)][72], d in [0,64)
    __shared__ float sbias[4][16];

    const int tid = threadIdx.x;
    const int warp = tid >> 5, lane = tid & 31;
    const int b = blockIdx.y;
    const int i0 = blockIdx.x * 32;
    const int r = lane >> 2, c = lane & 3;

    if (tid < 64) sbias[tid >> 4][tid & 15] = rels_bias[tid];  // [r][h]
    const int kmode = g_kpm_mode;

    float acc[2][8][4];
#pragma unroll
    for (int mt = 0; mt < 2; ++mt)
#pragma unroll
        for (int nt = 0; nt < 8; ++nt)
#pragma unroll
            for (int e = 0; e < 4; ++e) acc[mt][nt][e] = 0.f;

    const int ip = tid >> 4;   // 0..31 : i within tile (phase 1)
    const int jp = tid & 15;   // 0..15 : j within tile (phase 1)
    const int i1 = i0 + ip;
    const size_t sbase0 = (size_t)b * 16777216u + (size_t)i1 * 1024u;  // S
    const size_t mbase  = (size_t)b * 1048576u + (size_t)i1 * 1024u;   // masks
    const size_t wout0  = 4194304u;                                    // B*L*E

    const float* tvb = g_TV + (size_t)(b * 16 + warp) * 65536u;
    uint32_t* tsh = tvsh + warp * (16 * 72);
    const uint32_t* wh = wsh + warp * (32 * 20);

    for (int j0 = 0; j0 < 1024; j0 += 16) {
        __syncthreads();   // wsh reuse guard
        // ---- phase 1: softmax over heads, write w (global + smem tf32) ----
        {
            const int j = j0 + jp;
            float s[16];
            const size_t sb = sbase0 + j;
#pragma unroll
            for (int h = 0; h < 16; ++h) s[h] = g_S[sb + (size_t)h * 1048576u];
            const float4 rv = *reinterpret_cast<const float4*>(rels + (mbase + j) * 4);
            const float am = attn_mask[mbase + j];
            bool keep;
            if (kmode == 1)
                keep = reinterpret_cast<const unsigned char*>(kpm)[mbase + j] != 0;
            else if (kmode == 2)
                keep = reinterpret_cast<const unsigned short*>(kpm)[mbase + j] != 0;
            else
                keep = reinterpret_cast<const unsigned int*>(kpm)[mbase + j] != 0u;

            float mx = -1e30f;
#pragma unroll
            for (int h = 0; h < 16; ++h) {
                s[h] = (s[h] + rv.x * sbias[0][h] + rv.y * sbias[1][h]
                             + rv.z * sbias[2][h] + rv.w * sbias[3][h]) * 0.125f;
                mx = fmaxf(mx, s[h]);
            }
            float sum = 0.f;
#pragma unroll
            for (int h = 0; h < 16; ++h) { s[h] = __expf(s[h] - mx); sum += s[h]; }
            const float scale = keep ? (__expf(am) / sum) : 0.f;
#pragma unroll
            for (int h = 0; h < 16; ++h) {
                s[h] *= scale;
                wsh[h * (32 * 20) + ip * 20 + jp] = f2tf(s[h]);
            }
            float* wp = d_out + wout0 + (mbase + j) * 16;
#pragma unroll
            for (int h4 = 0; h4 < 4; ++h4) {
                float4 wv;
                wv.x = s[h4 * 4 + 0]; wv.y = s[h4 * 4 + 1];
                wv.z = s[h4 * 4 + 2]; wv.w = s[h4 * 4 + 3];
                reinterpret_cast<float4*>(wp)[h4] = wv;
            }
        }
        __syncthreads();
        // ---- phase 2: tensor-core PV (warp == head) ----
        {
            // stage tanh(V) j-tile into smem (tf32)
            const float* tv = tvb + (size_t)j0 * 64;
#pragma unroll
            for (int it = 0; it < 8; ++it) {
                int jj = it * 2 + (lane >> 4);
                int dd = (lane & 15) * 4;
                float4 t = *reinterpret_cast<const float4*>(tv + jj * 64 + dd);
                uint32_t* p = tsh + jj * 72 + dd;
                p[0] = f2tf(t.x); p[1] = f2tf(t.y);
                p[2] = f2tf(t.z); p[3] = f2tf(t.w);
            }
            __syncwarp();

            uint32_t af[2][2][4];
#pragma unroll
            for (int mt = 0; mt < 2; ++mt)
#pragma unroll
                for (int kt = 0; kt < 2; ++kt) {
                    const uint32_t* base = wh + (mt * 16 + r) * 20 + kt * 8 + c;
                    af[mt][kt][0] = base[0];
                    af[mt][kt][1] = base[8 * 20];
                    af[mt][kt][2] = base[4];
                    af[mt][kt][3] = base[8 * 20 + 4];
                }
#pragma unroll
            for (int kt = 0; kt < 2; ++kt)
#pragma unroll
                for (int nt = 0; nt < 8; ++nt) {
                    uint32_t bf[2];
                    bf[0] = tsh[(kt * 8 + c) * 72 + nt * 8 + r];
                    bf[1] = tsh[(kt * 8 + c + 4) * 72 + nt * 8 + r];
#pragma unroll
                    for (int mt = 0; mt < 2; ++mt)
                        mma_tf32(acc[mt][nt], af[mt][kt], bf);
                }
            __syncwarp();   // tsh reuse guard within warp
        }
    }

    // ---- epilogue: gate with sigmoid(g), store for final projection ----
#pragma unroll
    for (int mt = 0; mt < 2; ++mt)
#pragma unroll
        for (int nt = 0; nt < 8; ++nt) {
            size_t base0 = ((size_t)(b * 1024 + i0 + mt * 16 + r)) * 1024
                         + warp * 64 + nt * 8 + 2 * c;
            float2 sg0 = *reinterpret_cast<const float2*>(g_SG + base0);
            float2 o0;
            o0.x = acc[mt][nt][0] * sg0.x;
            o0.y = acc[mt][nt][1] * sg0.y;
            *reinterpret_cast<float2*>(g_gated + base0) = o0;
            size_t base1 = base0 + 8 * 1024;
            float2 sg1 = *reinterpret_cast<const float2*>(g_SG + base1);
            float2 o1;
            o1.x = acc[mt][nt][2] * sg1.x;
            o1.y = acc[mt][nt][3] * sg1.y;
            *reinterpret_cast<float2*>(g_gated + base1) = o1;
        }
}

// ---------------------------------------------------------------------------
// launch
// ---------------------------------------------------------------------------
extern "C" void kernel_launch(void* const* d_in, const int* in_sizes, int n_in,
                              void* d_out, int out_size) {
    (void)in_sizes; (void)n_in; (void)out_size;
    const float* query     = (const float*)d_in[0];
    const float* rels      = (const float*)d_in[1];
    const float* attn_mask = (const float*)d_in[2];
    const void*  kpm       = d_in[3];
    const float* proj_w    = (const float*)d_in[4];
    const float* proj_b    = (const float*)d_in[5];
    const float* out_w     = (const float*)d_in[6];
    const float* out_b     = (const float*)d_in[7];
    const float* rels_bias = (const float*)d_in[8];
    float* out = (float*)d_out;

    static bool attr_done = false;
    if (!attr_done) {
        cudaFuncSetAttribute(attn_wpv_kernel,
                             cudaFuncAttributeMaxDynamicSharedMemorySize, K3_SMEM);
        attr_done = true;
    }

    detect_kpm_kernel<<<1, 256>>>((const unsigned int*)kpm);
    gemm_tf32_kernel<<<dim3(32, 32, 1), 256>>>(0, query, proj_w, proj_b, nullptr);
    gemm_tf32_kernel<<<dim3(8, 8, 64), 256>>>(1, nullptr, nullptr, nullptr, nullptr);
    attn_wpv_kernel<<<dim3(32, 4, 1), 512, K3_SMEM>>>(rels, attn_mask, kpm, rels_bias, out);
    gemm_tf32_kernel<<<dim3(8, 32, 1), 256>>>(2, nullptr, out_w, out_b, out);
}